// round 5
// baseline (speedup 1.0000x reference)
#include <cuda_runtime.h>
#include <cstdint>

// x: (B=16, C=256, L=16384) fp32, kernel=4, stride=4 -> out (B, 256, 4096) fp32
#define C_CH    256
#define L_IN    16384
#define OUT_LEN 4096
#define EPS_F   1e-7f
#define T_TILES 4          // column-tiles per block (8 cols each -> 32 cols/block)
#define BUF_FLOATS (C_CH * 32)   // 256 ch x 8 cols x 4 floats = 8192 floats = 32 KB

// smem layout (floats): buf[2][8192] | red[8][8][10] | gsum[8][10] | cf[8][4]
#define SMEM_RED   (2 * BUF_FLOATS)
#define SMEM_GSUM  (SMEM_RED + 8 * 8 * 10)
#define SMEM_CF    (SMEM_GSUM + 8 * 10)
#define SMEM_FLOATS (SMEM_CF + 8 * 4)

__device__ __forceinline__ void cp_async16(uint32_t dst_smem, const void* src) {
    asm volatile("cp.async.cg.shared.global [%0], [%1], 16;"
                 :: "r"(dst_smem), "l"(src));
}
__device__ __forceinline__ void cp_commit() {
    asm volatile("cp.async.commit_group;");
}
__device__ __forceinline__ void cp_wait0() {
    asm volatile("cp.async.wait_group 0;");
}

// Block: 256 threads = 8 warps. Per tile: 8 output columns x 256 channels.
// Thread t: column j = t&7, channel group cg = t>>3 (0..31), channels cg+32i.
// Pipeline: cp.async next tile (gmem->smem) overlaps the current tile's
// reduction tail + epilogue, so the DRAM read stream never drains.
__global__ __launch_bounds__(256) void hpool_kernel(
    const float* __restrict__ x, float* __restrict__ out)
{
    extern __shared__ float smem[];
    const int t    = threadIdx.x;
    const int j    = t & 7;
    const int lane = t & 31;
    const int warp = t >> 5;
    const int cg   = t >> 3;
    const int b    = blockIdx.y;
    const int col_base = blockIdx.x * (8 * T_TILES);

    const uint32_t sbase = (uint32_t)__cvta_generic_to_shared(smem);
    // this thread's slot within a buffer: ((ch)*8 + j) * 16 bytes, ch = cg+32i
    const uint32_t slot0 = ((uint32_t)(cg * 8 + j)) * 16u;
    const float* gbase = x + (size_t)b * (C_CH * L_IN) + (size_t)col_base * 4 + j * 4;

    // ---- prologue: fetch tile 0 into buffer 0 ----
#pragma unroll
    for (int i = 0; i < 8; i++) {
        cp_async16(sbase + slot0 + (uint32_t)(32 * i) * 128u,
                   gbase + (size_t)(cg + 32 * i) * L_IN);
    }
    cp_commit();
    cp_wait0();
    __syncthreads();

#pragma unroll
    for (int k = 0; k < T_TILES; k++) {
        const int bufsel = k & 1;
        const uint32_t buf_off = (uint32_t)bufsel * (BUF_FLOATS * 4);

        // ---- issue next tile's copies (overlap everything below) ----
        if (k + 1 < T_TILES) {
            const float* gnext = gbase + (size_t)(k + 1) * 32;  // 8 cols * 4
            const uint32_t nbuf = (uint32_t)(bufsel ^ 1) * (BUF_FLOATS * 4);
#pragma unroll
            for (int i = 0; i < 8; i++) {
                cp_async16(sbase + nbuf + slot0 + (uint32_t)(32 * i) * 128u,
                           gnext + (size_t)(cg + 32 * i) * L_IN);
            }
        }
        cp_commit();

        // ---- read this tile's window from smem ----
        float4 w[8];
        const float* bufp = smem + bufsel * BUF_FLOATS;
#pragma unroll
        for (int i = 0; i < 8; i++) {
            w[i] = *reinterpret_cast<const float4*>(bufp + (cg + 32 * i) * 32 + j * 4);
        }

        // ---- Gram partials ----
        float s[10];
#pragma unroll
        for (int q = 0; q < 10; q++) s[q] = 0.f;
#pragma unroll
        for (int i = 0; i < 8; i++) {
            const float a0 = w[i].x, a1 = w[i].y, a2 = w[i].z, a3 = w[i].w;
            s[0] += a0 * a0; s[1] += a1 * a1; s[2] += a2 * a2; s[3] += a3 * a3;
            s[4] += a0 * a1; s[5] += a0 * a2; s[6] += a0 * a3;
            s[7] += a1 * a2; s[8] += a1 * a3; s[9] += a2 * a3;
        }
#pragma unroll
        for (int q = 0; q < 10; q++) {
            s[q] += __shfl_xor_sync(0xffffffffu, s[q], 8);
            s[q] += __shfl_xor_sync(0xffffffffu, s[q], 16);
        }

        float* red  = smem + SMEM_RED;   // [warp][col][q]
        float* gsum = smem + SMEM_GSUM;  // [col][q]
        float* cf   = smem + SMEM_CF;    // [col][p]
        if (lane < 8) {
#pragma unroll
            for (int q = 0; q < 10; q++) red[(warp * 8 + lane) * 10 + q] = s[q];
        }
        __syncthreads();

        if (t < 80) {
            const int col = t / 10, q = t % 10;
            float v = 0.f;
#pragma unroll
            for (int wq = 0; wq < 8; wq++) v += red[(wq * 8 + col) * 10 + q];
            gsum[col * 10 + q] = v;
        }
        __syncthreads();

        if (t < 8) {
            float G[10];
#pragma unroll
            for (int q = 0; q < 10; q++) G[q] = gsum[t * 10 + q];

            float f[4], gam[4], denom = 0.f;
#pragma unroll
            for (int p = 0; p < 4; p++) {
                f[p] = 2.0f / (1.0f + G[p]);
                gam[p] = rsqrtf(fmaxf(1.0f - f[p] * f[p] * G[p], EPS_F));
                denom += gam[p];
            }
            const float inv_d = 1.0f / denom;
            const float c0 = gam[0] * f[0] * inv_d;
            const float c1 = gam[1] * f[1] * inv_d;
            const float c2 = gam[2] * f[2] * inv_d;
            const float c3 = gam[3] * f[3] * inv_d;

            const float mk2 =
                c0 * c0 * G[0] + c1 * c1 * G[1] + c2 * c2 * G[2] + c3 * c3 * G[3] +
                2.0f * (c0 * c1 * G[4] + c0 * c2 * G[5] + c0 * c3 * G[6] +
                        c1 * c2 * G[7] + c1 * c3 * G[8] + c2 * c3 * G[9]);

            const float sc = 1.0f / (1.0f + sqrtf(fmaxf(1.0f - mk2, EPS_F)));
            cf[t * 4 + 0] = c0 * sc;
            cf[t * 4 + 1] = c1 * sc;
            cf[t * 4 + 2] = c2 * sc;
            cf[t * 4 + 3] = c3 * sc;
        }
        __syncthreads();

        // ---- epilogue: out = sum_p cf[j][p] * w[:,p] ----
        const float c0 = cf[j * 4 + 0], c1 = cf[j * 4 + 1];
        const float c2 = cf[j * 4 + 2], c3 = cf[j * 4 + 3];
        const size_t base_out = (size_t)b * (C_CH * OUT_LEN)
                              + (size_t)(col_base + k * 8 + j);
#pragma unroll
        for (int i = 0; i < 8; i++) {
            out[base_out + (size_t)(cg + 32 * i) * OUT_LEN] =
                c0 * w[i].x + c1 * w[i].y + c2 * w[i].z + c3 * w[i].w;
        }

        // ---- next tile's data must be resident before reuse ----
        cp_wait0();
        __syncthreads();
    }
}

extern "C" void kernel_launch(void* const* d_in, const int* in_sizes, int n_in,
                              void* d_out, int out_size)
{
    const float* x = (const float*)d_in[0];
    float* out = (float*)d_out;

    const int B = in_sizes[0] / (C_CH * L_IN);   // 16
    const int smem_bytes = SMEM_FLOATS * 4;      // ~68.5 KB

    static bool attr_set = false;
    if (!attr_set) {
        cudaFuncSetAttribute(hpool_kernel,
                             cudaFuncAttributeMaxDynamicSharedMemorySize,
                             smem_bytes);
        attr_set = true;
    }

    dim3 grid(OUT_LEN / (8 * T_TILES), B);       // (128, 16)
    hpool_kernel<<<grid, 256, smem_bytes>>>(x, out);
}